// round 12
// baseline (speedup 1.0000x reference)
#include <cuda_runtime.h>
#include <cstdint>

#define T_STEPS 2048
#define HID 64
#define EPB 7
#define NTHR 512
#define Q (EPB * HID)            // 448 floats per slot

typedef unsigned long long u64;

// ---------- f32x2 packed math ----------
__device__ __forceinline__ u64 fma2(u64 a, u64 b, u64 c) {
    u64 d; asm("fma.rn.f32x2 %0, %1, %2, %3;" : "=l"(d) : "l"(a), "l"(b), "l"(c)); return d;
}
__device__ __forceinline__ u64 mul2(u64 a, u64 b) {
    u64 d; asm("mul.rn.f32x2 %0, %1, %2;" : "=l"(d) : "l"(a), "l"(b)); return d;
}
__device__ __forceinline__ u64 pack2(float lo, float hi) {
    u64 d; asm("mov.b64 %0, {%1, %2};" : "=l"(d) : "f"(lo), "f"(hi)); return d;
}
__device__ __forceinline__ float2 unpack2(u64 v) {
    float a, b; asm("mov.b64 {%0, %1}, %2;" : "=f"(a), "=f"(b) : "l"(v));
    return make_float2(a, b);
}

// ---------- fast activations: MUFU.TANH ----------
__device__ __forceinline__ float tanh_fast(float x) {
    float r; asm("tanh.approx.f32 %0, %1;" : "=f"(r) : "f"(x)); return r;
}
__device__ __forceinline__ float sig_fast(float x) {
    return fmaf(tanh_fast(0.5f * x), 0.5f, 0.5f);
}

extern __shared__ float smem_f[];
// SMEM layout (float offsets)
#define OX   0                          // x: [EPB][T_STEPS]
#define OH1  (EPB * T_STEPS)            // h1: [2][Q]
#define OH2  (OH1 + 2 * Q)              // h2: [2][Q]
#define OP0  (OH2 + 2 * Q)              // psh0: [8][Q] float2
#define OP1  (OP0 + 2 * 8 * Q)          // psh1: [8][Q] float2
#define SMEM_FLOATS (OP1 + 2 * 8 * Q)   // 121856 B

// Phase-1 body. SEEDED is a compile-time literal: seeded path folds bias + x*Wih0.
#define PHASE1_LOOP(SEEDED, HP1, HP2)                                             \
    _Pragma("unroll")                                                             \
    for (int e = 0; e < EPB; ++e) {                                               \
        const int eo = e * 16;                                                    \
        u64 aA, aB, bA, bB;                                                       \
        ulonglong2 p = (HP1)[eo + 0], r = (HP1)[eo + 1];                          \
        if (SEEDED) {                                                             \
            float xv = xs[e * T_STEPS + j];                                       \
            aA = fma2(p.x, w0A[0], pack2(fmaf(xv, xwA, b0A), 0.0f));              \
            aB = fma2(p.x, w0B[0], pack2(fmaf(xv, xwB, b0B), 0.0f));              \
            bA = fma2(p.x, w1A[0], b1A2);                                         \
            bB = fma2(p.x, w1B[0], b1B2);                                         \
        } else {                                                                  \
            aA = mul2(p.x, w0A[0]); aB = mul2(p.x, w0B[0]);                       \
            bA = mul2(p.x, w1A[0]); bB = mul2(p.x, w1B[0]);                       \
        }                                                                         \
        aA = fma2(p.y, w0A[1], aA); aB = fma2(p.y, w0B[1], aB);                   \
        aA = fma2(r.x, w0A[2], aA); aB = fma2(r.x, w0B[2], aB);                   \
        aA = fma2(r.y, w0A[3], aA); aB = fma2(r.y, w0B[3], aB);                   \
        bA = fma2(p.y, w1A[1], bA); bB = fma2(p.y, w1B[1], bB);                   \
        bA = fma2(r.x, w1A[2], bA); bB = fma2(r.x, w1B[2], bB);                   \
        bA = fma2(r.y, w1A[3], bA); bB = fma2(r.y, w1B[3], bB);                   \
        p = (HP1)[eo + 2]; r = (HP1)[eo + 3];                                     \
        aA = fma2(p.x, w0A[4], aA); aB = fma2(p.x, w0B[4], aB);                   \
        aA = fma2(p.y, w0A[5], aA); aB = fma2(p.y, w0B[5], aB);                   \
        aA = fma2(r.x, w0A[6], aA); aB = fma2(r.x, w0B[6], aB);                   \
        aA = fma2(r.y, w0A[7], aA); aB = fma2(r.y, w0B[7], aB);                   \
        bA = fma2(p.x, w1A[4], bA); bB = fma2(p.x, w1B[4], bB);                   \
        bA = fma2(p.y, w1A[5], bA); bB = fma2(p.y, w1B[5], bB);                   \
        bA = fma2(r.x, w1A[6], bA); bB = fma2(r.x, w1B[6], bB);                   \
        bA = fma2(r.y, w1A[7], bA); bB = fma2(r.y, w1B[7], bB);                   \
        {                                                                         \
            float2 fa = unpack2(aA), fb = unpack2(aB);                            \
            pw0[e * HID] = make_float2(fa.x + fa.y, fb.x + fb.y);                 \
        }                                                                         \
        p = (HP2)[eo + 0]; r = (HP2)[eo + 1];                                     \
        bA = fma2(p.x, w1A[8],  bA); bB = fma2(p.x, w1B[8],  bB);                 \
        bA = fma2(p.y, w1A[9],  bA); bB = fma2(p.y, w1B[9],  bB);                 \
        bA = fma2(r.x, w1A[10], bA); bB = fma2(r.x, w1B[10], bB);                 \
        bA = fma2(r.y, w1A[11], bA); bB = fma2(r.y, w1B[11], bB);                 \
        p = (HP2)[eo + 2]; r = (HP2)[eo + 3];                                     \
        bA = fma2(p.x, w1A[12], bA); bB = fma2(p.x, w1B[12], bB);                 \
        bA = fma2(p.y, w1A[13], bA); bB = fma2(p.y, w1B[13], bB);                 \
        bA = fma2(r.x, w1A[14], bA); bB = fma2(r.x, w1B[14], bB);                 \
        bA = fma2(r.y, w1A[15], bA); bB = fma2(r.y, w1B[15], bB);                 \
        {                                                                         \
            float2 ga = unpack2(bA), gb = unpack2(bB);                            \
            pw1[e * HID] = make_float2(ga.x + ga.y, gb.x + gb.y);                 \
        }                                                                         \
    }

__global__ void __launch_bounds__(NTHR, 1)
lstm_fused(const float* __restrict__ x,
           const float* __restrict__ Wih0, const float* __restrict__ Whh0,
           const float* __restrict__ bih0, const float* __restrict__ bhh0,
           const float* __restrict__ Wih1, const float* __restrict__ Whh1,
           const float* __restrict__ bih1, const float* __restrict__ bhh1,
           const float* __restrict__ fcW,  const float* __restrict__ fcb,
           float* __restrict__ out, int B)
{
    float*  xs   = smem_f + OX;
    float*  h1f  = smem_f + OH1;
    float*  h2f  = smem_f + OH2;
    float2* psh0 = (float2*)(smem_f + OP0);
    float2* psh1 = (float2*)(smem_f + OP1);

    const int tid = threadIdx.x;
    const int u   = tid & 63;
    const int gp  = (tid >> 6) & 1;
    const int s   = tid >> 7;
    const int q   = s * 2 + gp;          // 0..7, warp-uniform
    const int b0e = blockIdx.x * EPB;

    // ---- stage x rows ----
    for (int i = tid; i < EPB * T_STEPS / 4; i += NTHR) {
        int e = i / (T_STEPS / 4), c = i % (T_STEPS / 4);
        int be = b0e + e; if (be > B - 1) be = B - 1;
        ((float4*)xs)[i] = ((const float4*)(x + (size_t)be * T_STEPS))[c];
    }
    for (int i = tid; i < 2 * Q; i += NTHR) { h1f[i] = 0.0f; h2f[i] = 0.0f; }

    // ---- register weights (k-window [16s,16s+16) for BOTH layers) ----
    const int rA = (gp * 2) * 64 + u, rB = (gp * 2 + 1) * 64 + u;
    const int k0 = s * 16;
    u64 w0A[8], w0B[8];
#pragma unroll
    for (int p = 0; p < 8; ++p) {
        w0A[p] = pack2(Whh0[rA * 64 + k0 + 2 * p], Whh0[rA * 64 + k0 + 2 * p + 1]);
        w0B[p] = pack2(Whh0[rB * 64 + k0 + 2 * p], Whh0[rB * 64 + k0 + 2 * p + 1]);
    }
    u64 w1A[16], w1B[16];
#pragma unroll
    for (int p = 0; p < 8; ++p) {
        w1A[p]     = pack2(Wih1[rA * 64 + k0 + 2 * p], Wih1[rA * 64 + k0 + 2 * p + 1]);
        w1B[p]     = pack2(Wih1[rB * 64 + k0 + 2 * p], Wih1[rB * 64 + k0 + 2 * p + 1]);
        w1A[8 + p] = pack2(Whh1[rA * 64 + k0 + 2 * p], Whh1[rA * 64 + k0 + 2 * p + 1]);
        w1B[8 + p] = pack2(Whh1[rB * 64 + k0 + 2 * p], Whh1[rB * 64 + k0 + 2 * p + 1]);
    }
    const float b0A = bih0[rA] + bhh0[rA], b0B = bih0[rB] + bhh0[rB];
    const float xwA = Wih0[rA],            xwB = Wih0[rB];
    const u64  b1A2 = pack2(bih1[rA] + bhh1[rA], 0.0f);
    const u64  b1B2 = pack2(bih1[rB] + bhh1[rB], 0.0f);

    float2* pw0 = psh0 + q * Q + u;
    float2* pw1 = psh1 + q * Q + u;
    const bool t0L1 = (q == 7);
    const int  e0   = t0L1 ? 0 : q;
    const float2* pr0 = (t0L1 ? psh1 : psh0) + e0 * HID + u;
    float*        hs0 = (t0L1 ? h2f : h1f) + e0 * HID + u;
    const bool has1 = (q < 6);
    const int  e1   = has1 ? (q + 1) : 0;
    const float2* pr1 = psh1 + e1 * HID + u;
    float*        hs1 = h2f + e1 * HID + u;

    // phase-1 read bases for both parities (pointer swap, no per-step mults)
    const ulonglong2* hp1_0 = (const ulonglong2*)h1f + s * 4;
    const ulonglong2* hp1_1 = (const ulonglong2*)(h1f + Q) + s * 4;
    const ulonglong2* hp2_0 = (const ulonglong2*)h2f + s * 4;
    const ulonglong2* hp2_1 = (const ulonglong2*)(h2f + Q) + s * 4;

    float cA = 0.0f, cB = 0.0f;
    __syncthreads();

#pragma unroll 1
    for (int j = 0; j < T_STEPS; ++j) {
        const int rb = j & 1;
        const ulonglong2* hp1 = rb ? hp1_1 : hp1_0;
        const ulonglong2* hp2 = rb ? hp2_1 : hp2_0;

        // ========== phase 1 (fused; specialized per s, no per-e branch) ==========
        if (s == 0) {
            PHASE1_LOOP(true, hp1, hp2)
        } else {
            PHASE1_LOOP(false, hp1, hp2)
        }
        __syncthreads();

        // ========== phase 2 ==========
        const int wo = (rb ^ 1) * Q;
        const bool act0 = t0L1 ? (j > 0) : true;
        if (act0) {
            float2 a0 = pr0[0 * Q], a1 = pr0[2 * Q], a2 = pr0[4 * Q], a3 = pr0[6 * Q];
            float2 g0 = pr0[1 * Q], g1 = pr0[3 * Q], g2 = pr0[5 * Q], g3 = pr0[7 * Q];
            float pi = a0.x + a1.x + a2.x + a3.x;
            float pf = a0.y + a1.y + a2.y + a3.y;
            float pg = g0.x + g1.x + g2.x + g3.x;
            float po = g0.y + g1.y + g2.y + g3.y;
            float gi = sig_fast(pi), gf = sig_fast(pf);
            float gg = tanh_fast(pg), go = sig_fast(po);
            cA = gf * cA + gi * gg;
            hs0[wo] = go * tanh_fast(cA);
        }
        if (has1 && j > 0) {
            float2 a0 = pr1[0 * Q], a1 = pr1[2 * Q], a2 = pr1[4 * Q], a3 = pr1[6 * Q];
            float2 g0 = pr1[1 * Q], g1 = pr1[3 * Q], g2 = pr1[5 * Q], g3 = pr1[7 * Q];
            float pi = a0.x + a1.x + a2.x + a3.x;
            float pf = a0.y + a1.y + a2.y + a3.y;
            float pg = g0.x + g1.x + g2.x + g3.x;
            float po = g0.y + g1.y + g2.y + g3.y;
            float gi = sig_fast(pi), gf = sig_fast(pf);
            float gg = tanh_fast(pg), go = sig_fast(po);
            cB = gf * cB + gi * gg;
            hs1[wo] = go * tanh_fast(cB);
        }
        __syncthreads();
    }

    // ========== tail: L1 step T-1 (h1[T-1], h2[T-2] in slot 0) ==========
    {
        const ulonglong2* hp1 = hp1_0;
        const ulonglong2* hp2 = hp2_0;
#pragma unroll
        for (int e = 0; e < EPB; ++e) {
            const int eo = e * 16;
            u64 bA, bB;
            ulonglong2 p = hp1[eo + 0], r = hp1[eo + 1];
            if (s == 0) {
                bA = fma2(p.x, w1A[0], b1A2);
                bB = fma2(p.x, w1B[0], b1B2);
            } else {
                bA = mul2(p.x, w1A[0]);
                bB = mul2(p.x, w1B[0]);
            }
            bA = fma2(p.y, w1A[1], bA); bB = fma2(p.y, w1B[1], bB);
            bA = fma2(r.x, w1A[2], bA); bB = fma2(r.x, w1B[2], bB);
            bA = fma2(r.y, w1A[3], bA); bB = fma2(r.y, w1B[3], bB);
            p = hp1[eo + 2]; r = hp1[eo + 3];
            bA = fma2(p.x, w1A[4], bA); bB = fma2(p.x, w1B[4], bB);
            bA = fma2(p.y, w1A[5], bA); bB = fma2(p.y, w1B[5], bB);
            bA = fma2(r.x, w1A[6], bA); bB = fma2(r.x, w1B[6], bB);
            bA = fma2(r.y, w1A[7], bA); bB = fma2(r.y, w1B[7], bB);
            p = hp2[eo + 0]; r = hp2[eo + 1];
            bA = fma2(p.x, w1A[8],  bA); bB = fma2(p.x, w1B[8],  bB);
            bA = fma2(p.y, w1A[9],  bA); bB = fma2(p.y, w1B[9],  bB);
            bA = fma2(r.x, w1A[10], bA); bB = fma2(r.x, w1B[10], bB);
            bA = fma2(r.y, w1A[11], bA); bB = fma2(r.y, w1B[11], bB);
            p = hp2[eo + 2]; r = hp2[eo + 3];
            bA = fma2(p.x, w1A[12], bA); bB = fma2(p.x, w1B[12], bB);
            bA = fma2(p.y, w1A[13], bA); bB = fma2(p.y, w1B[13], bB);
            bA = fma2(r.x, w1A[14], bA); bB = fma2(r.x, w1B[14], bB);
            bA = fma2(r.y, w1A[15], bA); bB = fma2(r.y, w1B[15], bB);
            float2 ga = unpack2(bA), gb = unpack2(bB);
            pw1[e * HID] = make_float2(ga.x + ga.y, gb.x + gb.y);
        }
    }
    __syncthreads();
    {
        if (t0L1) {
            float2 a0 = pr0[0 * Q], a1 = pr0[2 * Q], a2 = pr0[4 * Q], a3 = pr0[6 * Q];
            float2 g0 = pr0[1 * Q], g1 = pr0[3 * Q], g2 = pr0[5 * Q], g3 = pr0[7 * Q];
            float pi = a0.x + a1.x + a2.x + a3.x;
            float pf = a0.y + a1.y + a2.y + a3.y;
            float pg = g0.x + g1.x + g2.x + g3.x;
            float po = g0.y + g1.y + g2.y + g3.y;
            float gi = sig_fast(pi), gf = sig_fast(pf);
            float gg = tanh_fast(pg), go = sig_fast(po);
            cA = gf * cA + gi * gg;
            hs0[Q] = go * tanh_fast(cA);
        }
        if (has1) {
            float2 a0 = pr1[0 * Q], a1 = pr1[2 * Q], a2 = pr1[4 * Q], a3 = pr1[6 * Q];
            float2 g0 = pr1[1 * Q], g1 = pr1[3 * Q], g2 = pr1[5 * Q], g3 = pr1[7 * Q];
            float pi = a0.x + a1.x + a2.x + a3.x;
            float pf = a0.y + a1.y + a2.y + a3.y;
            float pg = g0.x + g1.x + g2.x + g3.x;
            float po = g0.y + g1.y + g2.y + g3.y;
            float gi = sig_fast(pi), gf = sig_fast(pf);
            float gg = tanh_fast(pg), go = sig_fast(po);
            cB = gf * cB + gi * gg;
            hs1[Q] = go * tanh_fast(cB);
        }
    }
    __syncthreads();

    // ---- final FC ----
    if (tid < EPB * 32) {
        const int e = tid >> 5, lane = tid & 31;
        const float* h2l = h2f + Q + e * HID;
        float acc = h2l[lane] * fcW[lane] + h2l[32 + lane] * fcW[32 + lane];
#pragma unroll
        for (int o = 16; o > 0; o >>= 1)
            acc += __shfl_down_sync(0xFFFFFFFFu, acc, o);
        if (lane == 0) {
            int be = b0e + e; if (be > B - 1) be = B - 1;
            out[be] = acc + fcb[0];
        }
    }
}

extern "C" void kernel_launch(void* const* d_in, const int* in_sizes, int n_in,
                              void* d_out, int out_size)
{
    const float* x    = (const float*)d_in[0];
    const float* Wih0 = (const float*)d_in[1];
    const float* Whh0 = (const float*)d_in[2];
    const float* bih0 = (const float*)d_in[3];
    const float* bhh0 = (const float*)d_in[4];
    const float* Wih1 = (const float*)d_in[5];
    const float* Whh1 = (const float*)d_in[6];
    const float* bih1 = (const float*)d_in[7];
    const float* bhh1 = (const float*)d_in[8];
    const float* fcW  = (const float*)d_in[9];
    const float* fcb  = (const float*)d_in[10];
    float* out = (float*)d_out;

    int B = in_sizes[0] / T_STEPS;
    if (B < 1) B = 1;
    int blocks = (B + EPB - 1) / EPB;

    const int smem_bytes = SMEM_FLOATS * 4;
    cudaFuncSetAttribute(lstm_fused, cudaFuncAttributeMaxDynamicSharedMemorySize,
                         smem_bytes);

    lstm_fused<<<blocks, NTHR, smem_bytes>>>(x, Wih0, Whh0, bih0, bhh0,
                                             Wih1, Whh1, bih1, bhh1,
                                             fcW, fcb, out, B);
}

// round 13
// speedup vs baseline: 1.0688x; 1.0688x over previous
#include <cuda_runtime.h>
#include <cstdint>

#define T_STEPS 2048
#define HID 64
#define EPB 7
#define NTHR 512
#define Q (EPB * HID)            // 448 floats per slot

typedef unsigned long long u64;

// ---------- f32x2 packed math ----------
__device__ __forceinline__ u64 fma2(u64 a, u64 b, u64 c) {
    u64 d; asm("fma.rn.f32x2 %0, %1, %2, %3;" : "=l"(d) : "l"(a), "l"(b), "l"(c)); return d;
}
__device__ __forceinline__ u64 mul2(u64 a, u64 b) {
    u64 d; asm("mul.rn.f32x2 %0, %1, %2;" : "=l"(d) : "l"(a), "l"(b)); return d;
}
__device__ __forceinline__ u64 pack2(float lo, float hi) {
    u64 d; asm("mov.b64 %0, {%1, %2};" : "=l"(d) : "f"(lo), "f"(hi)); return d;
}
__device__ __forceinline__ float2 unpack2(u64 v) {
    float a, b; asm("mov.b64 {%0, %1}, %2;" : "=f"(a), "=f"(b) : "l"(v));
    return make_float2(a, b);
}

// ---------- fast activations: MUFU.TANH ----------
__device__ __forceinline__ float tanh_fast(float x) {
    float r; asm("tanh.approx.f32 %0, %1;" : "=f"(r) : "f"(x)); return r;
}
__device__ __forceinline__ float sig_fast(float x) {
    return fmaf(tanh_fast(0.5f * x), 0.5f, 0.5f);
}

extern __shared__ float smem_f[];
// SMEM layout (float offsets)
#define OX   0                          // x: [EPB][T_STEPS]
#define OH1  (EPB * T_STEPS)            // h1: [2][Q]
#define OH2  (OH1 + 2 * Q)              // h2: [2][Q]
#define OP0  (OH2 + 2 * Q)              // psh0: [8][Q] float2
#define OP1  (OP0 + 2 * 8 * Q)          // psh1: [8][Q] float2
#define SMEM_FLOATS (OP1 + 2 * 8 * Q)   // 121856 B

// Phase-1 body: uniform for ALL threads — mul2 starts, no seeds, no branches.
#define PHASE1_LOOP(HP1, HP2)                                                     \
    _Pragma("unroll")                                                             \
    for (int e = 0; e < EPB; ++e) {                                               \
        const int eo = e * 16;                                                    \
        u64 aA, aB, bA, bB;                                                       \
        ulonglong2 p = (HP1)[eo + 0], r = (HP1)[eo + 1];                          \
        aA = mul2(p.x, w0A[0]); aB = mul2(p.x, w0B[0]);                           \
        bA = mul2(p.x, w1A[0]); bB = mul2(p.x, w1B[0]);                           \
        aA = fma2(p.y, w0A[1], aA); aB = fma2(p.y, w0B[1], aB);                   \
        aA = fma2(r.x, w0A[2], aA); aB = fma2(r.x, w0B[2], aB);                   \
        aA = fma2(r.y, w0A[3], aA); aB = fma2(r.y, w0B[3], aB);                   \
        bA = fma2(p.y, w1A[1], bA); bB = fma2(p.y, w1B[1], bB);                   \
        bA = fma2(r.x, w1A[2], bA); bB = fma2(r.x, w1B[2], bB);                   \
        bA = fma2(r.y, w1A[3], bA); bB = fma2(r.y, w1B[3], bB);                   \
        p = (HP1)[eo + 2]; r = (HP1)[eo + 3];                                     \
        aA = fma2(p.x, w0A[4], aA); aB = fma2(p.x, w0B[4], aB);                   \
        aA = fma2(p.y, w0A[5], aA); aB = fma2(p.y, w0B[5], aB);                   \
        aA = fma2(r.x, w0A[6], aA); aB = fma2(r.x, w0B[6], aB);                   \
        aA = fma2(r.y, w0A[7], aA); aB = fma2(r.y, w0B[7], aB);                   \
        bA = fma2(p.x, w1A[4], bA); bB = fma2(p.x, w1B[4], bB);                   \
        bA = fma2(p.y, w1A[5], bA); bB = fma2(p.y, w1B[5], bB);                   \
        bA = fma2(r.x, w1A[6], bA); bB = fma2(r.x, w1B[6], bB);                   \
        bA = fma2(r.y, w1A[7], bA); bB = fma2(r.y, w1B[7], bB);                   \
        {                                                                         \
            float2 fa = unpack2(aA), fb = unpack2(aB);                            \
            pw0[e * HID] = make_float2(fa.x + fa.y, fb.x + fb.y);                 \
        }                                                                         \
        p = (HP2)[eo + 0]; r = (HP2)[eo + 1];                                     \
        bA = fma2(p.x, w1A[8],  bA); bB = fma2(p.x, w1B[8],  bB);                 \
        bA = fma2(p.y, w1A[9],  bA); bB = fma2(p.y, w1B[9],  bB);                 \
        bA = fma2(r.x, w1A[10], bA); bB = fma2(r.x, w1B[10], bB);                 \
        bA = fma2(r.y, w1A[11], bA); bB = fma2(r.y, w1B[11], bB);                 \
        p = (HP2)[eo + 2]; r = (HP2)[eo + 3];                                     \
        bA = fma2(p.x, w1A[12], bA); bB = fma2(p.x, w1B[12], bB);                 \
        bA = fma2(p.y, w1A[13], bA); bB = fma2(p.y, w1B[13], bB);                 \
        bA = fma2(r.x, w1A[14], bA); bB = fma2(r.x, w1B[14], bB);                 \
        bA = fma2(r.y, w1A[15], bA); bB = fma2(r.y, w1B[15], bB);                 \
        {                                                                         \
            float2 ga = unpack2(bA), gb = unpack2(bB);                            \
            pw1[e * HID] = make_float2(ga.x + ga.y, gb.x + gb.y);                 \
        }                                                                         \
    }

__global__ void __launch_bounds__(NTHR, 1)
lstm_fused(const float* __restrict__ x,
           const float* __restrict__ Wih0, const float* __restrict__ Whh0,
           const float* __restrict__ bih0, const float* __restrict__ bhh0,
           const float* __restrict__ Wih1, const float* __restrict__ Whh1,
           const float* __restrict__ bih1, const float* __restrict__ bhh1,
           const float* __restrict__ fcW,  const float* __restrict__ fcb,
           float* __restrict__ out, int B)
{
    float*  xs   = smem_f + OX;
    float*  h1f  = smem_f + OH1;
    float*  h2f  = smem_f + OH2;
    float2* psh0 = (float2*)(smem_f + OP0);
    float2* psh1 = (float2*)(smem_f + OP1);

    const int tid = threadIdx.x;
    const int u   = tid & 63;
    const int gp  = (tid >> 6) & 1;
    const int s   = tid >> 7;
    const int q   = s * 2 + gp;          // 0..7, warp-uniform
    const int b0e = blockIdx.x * EPB;

    // ---- stage x rows ----
    for (int i = tid; i < EPB * T_STEPS / 4; i += NTHR) {
        int e = i / (T_STEPS / 4), c = i % (T_STEPS / 4);
        int be = b0e + e; if (be > B - 1) be = B - 1;
        ((float4*)xs)[i] = ((const float4*)(x + (size_t)be * T_STEPS))[c];
    }
    for (int i = tid; i < 2 * Q; i += NTHR) { h1f[i] = 0.0f; h2f[i] = 0.0f; }

    // ---- register weights (k-window [16s,16s+16) for BOTH layers) ----
    const int rA = (gp * 2) * 64 + u, rB = (gp * 2 + 1) * 64 + u;
    const int k0 = s * 16;
    u64 w0A[8], w0B[8];
#pragma unroll
    for (int p = 0; p < 8; ++p) {
        w0A[p] = pack2(Whh0[rA * 64 + k0 + 2 * p], Whh0[rA * 64 + k0 + 2 * p + 1]);
        w0B[p] = pack2(Whh0[rB * 64 + k0 + 2 * p], Whh0[rB * 64 + k0 + 2 * p + 1]);
    }
    u64 w1A[16], w1B[16];
#pragma unroll
    for (int p = 0; p < 8; ++p) {
        w1A[p]     = pack2(Wih1[rA * 64 + k0 + 2 * p], Wih1[rA * 64 + k0 + 2 * p + 1]);
        w1B[p]     = pack2(Wih1[rB * 64 + k0 + 2 * p], Wih1[rB * 64 + k0 + 2 * p + 1]);
        w1A[8 + p] = pack2(Whh1[rA * 64 + k0 + 2 * p], Whh1[rA * 64 + k0 + 2 * p + 1]);
        w1B[8 + p] = pack2(Whh1[rB * 64 + k0 + 2 * p], Whh1[rB * 64 + k0 + 2 * p + 1]);
    }

    float2* pw0 = psh0 + q * Q + u;
    float2* pw1 = psh1 + q * Q + u;
    const bool t0L1 = (q == 7);
    const int  e0   = t0L1 ? 0 : q;
    const float2* pr0 = (t0L1 ? psh1 : psh0) + e0 * HID + u;
    float*        hs0 = (t0L1 ? h2f : h1f) + e0 * HID + u;
    const float*  xb0 = xs + e0 * T_STEPS;
    const bool has1 = (q < 6);
    const int  e1   = has1 ? (q + 1) : 0;
    const float2* pr1 = psh1 + e1 * HID + u;
    float*        hs1 = h2f + e1 * HID + u;

    // ---- phase-2 activation constants (per-thread registers) ----
    // L1 biases (task1 + t0L1 task0)
    const float b1i = bih1[u] + bhh1[u],             b1f = bih1[64 + u] + bhh1[64 + u];
    const float b1g = bih1[128 + u] + bhh1[128 + u], b1o = bih1[192 + u] + bhh1[192 + u];
    // task0 bias + x-weight (zeroed for L1 task so math is branch-free)
    const float tbi = t0L1 ? b1i : (bih0[u] + bhh0[u]);
    const float tbf = t0L1 ? b1f : (bih0[64 + u] + bhh0[64 + u]);
    const float tbg = t0L1 ? b1g : (bih0[128 + u] + bhh0[128 + u]);
    const float tbo = t0L1 ? b1o : (bih0[192 + u] + bhh0[192 + u]);
    const float xwi = t0L1 ? 0.0f : Wih0[u];
    const float xwf = t0L1 ? 0.0f : Wih0[64 + u];
    const float xwg = t0L1 ? 0.0f : Wih0[128 + u];
    const float xwo = t0L1 ? 0.0f : Wih0[192 + u];

    // phase-1 read bases for both parities (pointer swap)
    const ulonglong2* hp1_0 = (const ulonglong2*)h1f + s * 4;
    const ulonglong2* hp1_1 = (const ulonglong2*)(h1f + Q) + s * 4;
    const ulonglong2* hp2_0 = (const ulonglong2*)h2f + s * 4;
    const ulonglong2* hp2_1 = (const ulonglong2*)(h2f + Q) + s * 4;

    float cA = 0.0f, cB = 0.0f;
    __syncthreads();

#pragma unroll 1
    for (int j = 0; j < T_STEPS; ++j) {
        const int rb = j & 1;
        const ulonglong2* hp1 = rb ? hp1_1 : hp1_0;
        const ulonglong2* hp2 = rb ? hp2_1 : hp2_0;

        // ========== phase 1 (single uniform body) ==========
        PHASE1_LOOP(hp1, hp2)
        __syncthreads();

        // ========== phase 2 (bias + x*w folded here, branch-free) ==========
        const int wo = (rb ^ 1) * Q;
        const bool act0 = t0L1 ? (j > 0) : true;
        if (act0) {
            float2 a0 = pr0[0 * Q], a1 = pr0[2 * Q], a2 = pr0[4 * Q], a3 = pr0[6 * Q];
            float2 g0 = pr0[1 * Q], g1 = pr0[3 * Q], g2 = pr0[5 * Q], g3 = pr0[7 * Q];
            float xv = xb0[j];
            float pi = a0.x + a1.x + a2.x + a3.x + fmaf(xv, xwi, tbi);
            float pf = a0.y + a1.y + a2.y + a3.y + fmaf(xv, xwf, tbf);
            float pg = g0.x + g1.x + g2.x + g3.x + fmaf(xv, xwg, tbg);
            float po = g0.y + g1.y + g2.y + g3.y + fmaf(xv, xwo, tbo);
            float gi = sig_fast(pi), gf = sig_fast(pf);
            float gg = tanh_fast(pg), go = sig_fast(po);
            cA = gf * cA + gi * gg;
            hs0[wo] = go * tanh_fast(cA);
        }
        if (has1 && j > 0) {
            float2 a0 = pr1[0 * Q], a1 = pr1[2 * Q], a2 = pr1[4 * Q], a3 = pr1[6 * Q];
            float2 g0 = pr1[1 * Q], g1 = pr1[3 * Q], g2 = pr1[5 * Q], g3 = pr1[7 * Q];
            float pi = a0.x + a1.x + a2.x + a3.x + b1i;
            float pf = a0.y + a1.y + a2.y + a3.y + b1f;
            float pg = g0.x + g1.x + g2.x + g3.x + b1g;
            float po = g0.y + g1.y + g2.y + g3.y + b1o;
            float gi = sig_fast(pi), gf = sig_fast(pf);
            float gg = tanh_fast(pg), go = sig_fast(po);
            cB = gf * cB + gi * gg;
            hs1[wo] = go * tanh_fast(cB);
        }
        __syncthreads();
    }

    // ========== tail: L1 step T-1 (h1[T-1], h2[T-2] in slot 0) ==========
    {
        const ulonglong2* hp1 = hp1_0;
        const ulonglong2* hp2 = hp2_0;
#pragma unroll
        for (int e = 0; e < EPB; ++e) {
            const int eo = e * 16;
            u64 bA, bB;
            ulonglong2 p = hp1[eo + 0], r = hp1[eo + 1];
            bA = mul2(p.x, w1A[0]); bB = mul2(p.x, w1B[0]);
            bA = fma2(p.y, w1A[1], bA); bB = fma2(p.y, w1B[1], bB);
            bA = fma2(r.x, w1A[2], bA); bB = fma2(r.x, w1B[2], bB);
            bA = fma2(r.y, w1A[3], bA); bB = fma2(r.y, w1B[3], bB);
            p = hp1[eo + 2]; r = hp1[eo + 3];
            bA = fma2(p.x, w1A[4], bA); bB = fma2(p.x, w1B[4], bB);
            bA = fma2(p.y, w1A[5], bA); bB = fma2(p.y, w1B[5], bB);
            bA = fma2(r.x, w1A[6], bA); bB = fma2(r.x, w1B[6], bB);
            bA = fma2(r.y, w1A[7], bA); bB = fma2(r.y, w1B[7], bB);
            p = hp2[eo + 0]; r = hp2[eo + 1];
            bA = fma2(p.x, w1A[8],  bA); bB = fma2(p.x, w1B[8],  bB);
            bA = fma2(p.y, w1A[9],  bA); bB = fma2(p.y, w1B[9],  bB);
            bA = fma2(r.x, w1A[10], bA); bB = fma2(r.x, w1B[10], bB);
            bA = fma2(r.y, w1A[11], bA); bB = fma2(r.y, w1B[11], bB);
            p = hp2[eo + 2]; r = hp2[eo + 3];
            bA = fma2(p.x, w1A[12], bA); bB = fma2(p.x, w1B[12], bB);
            bA = fma2(p.y, w1A[13], bA); bB = fma2(p.y, w1B[13], bB);
            bA = fma2(r.x, w1A[14], bA); bB = fma2(r.x, w1B[14], bB);
            bA = fma2(r.y, w1A[15], bA); bB = fma2(r.y, w1B[15], bB);
            float2 ga = unpack2(bA), gb = unpack2(bB);
            pw1[e * HID] = make_float2(ga.x + ga.y, gb.x + gb.y);
        }
    }
    __syncthreads();
    {
        if (t0L1) {
            float2 a0 = pr0[0 * Q], a1 = pr0[2 * Q], a2 = pr0[4 * Q], a3 = pr0[6 * Q];
            float2 g0 = pr0[1 * Q], g1 = pr0[3 * Q], g2 = pr0[5 * Q], g3 = pr0[7 * Q];
            float pi = a0.x + a1.x + a2.x + a3.x + b1i;
            float pf = a0.y + a1.y + a2.y + a3.y + b1f;
            float pg = g0.x + g1.x + g2.x + g3.x + b1g;
            float po = g0.y + g1.y + g2.y + g3.y + b1o;
            float gi = sig_fast(pi), gf = sig_fast(pf);
            float gg = tanh_fast(pg), go = sig_fast(po);
            cA = gf * cA + gi * gg;
            hs0[Q] = go * tanh_fast(cA);
        }
        if (has1) {
            float2 a0 = pr1[0 * Q], a1 = pr1[2 * Q], a2 = pr1[4 * Q], a3 = pr1[6 * Q];
            float2 g0 = pr1[1 * Q], g1 = pr1[3 * Q], g2 = pr1[5 * Q], g3 = pr1[7 * Q];
            float pi = a0.x + a1.x + a2.x + a3.x + b1i;
            float pf = a0.y + a1.y + a2.y + a3.y + b1f;
            float pg = g0.x + g1.x + g2.x + g3.x + b1g;
            float po = g0.y + g1.y + g2.y + g3.y + b1o;
            float gi = sig_fast(pi), gf = sig_fast(pf);
            float gg = tanh_fast(pg), go = sig_fast(po);
            cB = gf * cB + gi * gg;
            hs1[Q] = go * tanh_fast(cB);
        }
    }
    __syncthreads();

    // ---- final FC ----
    if (tid < EPB * 32) {
        const int e = tid >> 5, lane = tid & 31;
        const float* h2l = h2f + Q + e * HID;
        float acc = h2l[lane] * fcW[lane] + h2l[32 + lane] * fcW[32 + lane];
#pragma unroll
        for (int o = 16; o > 0; o >>= 1)
            acc += __shfl_down_sync(0xFFFFFFFFu, acc, o);
        if (lane == 0) {
            int be = b0e + e; if (be > B - 1) be = B - 1;
            out[be] = acc + fcb[0];
        }
    }
}

extern "C" void kernel_launch(void* const* d_in, const int* in_sizes, int n_in,
                              void* d_out, int out_size)
{
    const float* x    = (const float*)d_in[0];
    const float* Wih0 = (const float*)d_in[1];
    const float* Whh0 = (const float*)d_in[2];
    const float* bih0 = (const float*)d_in[3];
    const float* bhh0 = (const float*)d_in[4];
    const float* Wih1 = (const float*)d_in[5];
    const float* Whh1 = (const float*)d_in[6];
    const float* bih1 = (const float*)d_in[7];
    const float* bhh1 = (const float*)d_in[8];
    const float* fcW  = (const float*)d_in[9];
    const float* fcb  = (const float*)d_in[10];
    float* out = (float*)d_out;

    int B = in_sizes[0] / T_STEPS;
    if (B < 1) B = 1;
    int blocks = (B + EPB - 1) / EPB;

    const int smem_bytes = SMEM_FLOATS * 4;
    cudaFuncSetAttribute(lstm_fused, cudaFuncAttributeMaxDynamicSharedMemorySize,
                         smem_bytes);

    lstm_fused<<<blocks, NTHR, smem_bytes>>>(x, Wih0, Whh0, bih0, bhh0,
                                             Wih1, Whh1, bih1, bhh1,
                                             fcW, fcb, out, B);
}